// round 5
// baseline (speedup 1.0000x reference)
#include <cuda_runtime.h>
#include <math.h>
#include <stdint.h>

#define NT   32768
#define DIMS 512
#define KC   4096

#define M_TILE 128
#define N_TILE 256
#define BK     128                              // int8 k per stage (128 bytes/row)
#define NITER  ((KC / N_TILE) * (DIMS / BK))    // 16 * 4 = 64
#define MARGIN 2.4e-3f
#define MAXCAND 32
#define E_SCALE 520192.0f                        // 127 * 4096 (|e| <= 1/4096)

// SMEM stage: A 128x128 s8 (16KB) + B 256x128 s8 (32KB) = 48KB; 3 stages.
#define SA_OFF   0
#define SB_OFF   16384
#define STG      49152
#define SM_SCR   (3 * STG)
#define SM_TOTAL (SM_SCR + 1024)                 // 148480

// ---------------- scratch (device globals; no mallocs allowed) ----------------
__device__ float   g_Sz[NT];
__device__ int     g_best[NT];
__device__ int     g_counts[KC];
__device__ double  g_loss;
__device__ int     g_zmax_bits;
__device__ int8_t  g_z8[NT * DIMS];
__device__ int8_t  g_e8[KC * DIMS];
__device__ int     g_cand[NT * MAXCAND];
__device__ int     g_ccount[NT];
__device__ int     g_ovf[NT];
__device__ int     g_ovf_n;

// ---------------- PTX helpers (compute_103-safe) ----------------
__device__ __forceinline__ uint32_t smem_u32(const void* p) {
    uint32_t a;
    asm("{ .reg .u64 t; cvta.to.shared.u64 t, %1; cvt.u32.u64 %0, t; }" : "=r"(a) : "l"(p));
    return a;
}
__device__ __forceinline__ void cp16(uint32_t dst, const void* src) {
    asm volatile("cp.async.cg.shared.global [%0], [%1], 16;" :: "r"(dst), "l"(src) : "memory");
}
#define CP_COMMIT() asm volatile("cp.async.commit_group;" ::: "memory")
#define CP_WAIT(n)  asm volatile("cp.async.wait_group %0;" :: "n"(n) : "memory")

__device__ __forceinline__ void ldsm4(uint32_t* r, uint32_t addr) {
    asm volatile("ldmatrix.sync.aligned.m8n8.x4.shared.b16 {%0,%1,%2,%3}, [%4];"
                 : "=r"(r[0]), "=r"(r[1]), "=r"(r[2]), "=r"(r[3]) : "r"(addr));
}
__device__ __forceinline__ void mma_s8(int* d, const uint32_t* a,
                                       uint32_t b0, uint32_t b1) {
    asm volatile(
        "mma.sync.aligned.m16n8k32.row.col.s32.s8.s8.s32 "
        "{%0,%1,%2,%3}, {%4,%5,%6,%7}, {%8,%9}, {%0,%1,%2,%3};"
        : "+r"(d[0]), "+r"(d[1]), "+r"(d[2]), "+r"(d[3])
        : "r"(a[0]), "r"(a[1]), "r"(a[2]), "r"(a[3]), "r"(b0), "r"(b1));
}

// ---------------------------------------------------------------------------
__global__ void k_init() {
    int t = blockIdx.x * blockDim.x + threadIdx.x;
    if (t < KC) g_counts[t] = 0;
    if (t == 0) { g_loss = 0.0; g_zmax_bits = 0; g_ovf_n = 0; }
}

// max |z| (positive-float bits compare as ints)
__global__ void k_zmax(const float* __restrict__ z) {
    float m = 0.0f;
    const int n4 = NT * DIMS / 4;
    for (int i = blockIdx.x * blockDim.x + threadIdx.x; i < n4; i += gridDim.x * blockDim.x) {
        float4 v = ((const float4*)z)[i];
        m = fmaxf(m, fmaxf(fmaxf(fabsf(v.x), fabsf(v.y)), fmaxf(fabsf(v.z), fabsf(v.w))));
    }
    #pragma unroll
    for (int o = 16; o; o >>= 1) m = fmaxf(m, __shfl_xor_sync(0xffffffffu, m, o));
    __shared__ float sm[8];
    if ((threadIdx.x & 31) == 0) sm[threadIdx.x >> 5] = m;
    __syncthreads();
    if (threadIdx.x == 0) {
        #pragma unroll
        for (int w = 1; w < 8; w++) m = fmaxf(m, sm[w]);
        atomicMax(&g_zmax_bits, __float_as_int(m));
    }
}

// fused: row norm (fp64) + int8 quantization of z. Warp per row.
__global__ void k_zq(const float* __restrict__ z) {
    const int row  = blockIdx.x * 8 + (threadIdx.x >> 5);
    const int lane = threadIdx.x & 31;
    const float s = 127.0f / __int_as_float(g_zmax_bits);
    const float* zr = z + (size_t)row * DIMS;
    uint32_t* outr = (uint32_t*)(g_z8 + (size_t)row * DIMS);

    double acc = 0.0;
    #pragma unroll
    for (int j = 0; j < 4; j++) {
        float4 v = *(const float4*)(zr + lane * 4 + 128 * j);
        acc += (double)v.x * v.x + (double)v.y * v.y
             + (double)v.z * v.z + (double)v.w * v.w;
        int q0 = __float2int_rn(v.x * s), q1 = __float2int_rn(v.y * s);
        int q2 = __float2int_rn(v.z * s), q3 = __float2int_rn(v.w * s);
        outr[lane + 32 * j] = (q0 & 0xff) | ((q1 & 0xff) << 8)
                            | ((q2 & 0xff) << 16) | ((q3 & 0xff) << 24);
    }
    #pragma unroll
    for (int o = 16; o; o >>= 1) acc += __shfl_down_sync(0xffffffffu, acc, o);
    if (lane == 0) g_Sz[row] = (float)acc;
}

// int8 quantization of emb (exact-range scale 127*4096). Warp per row.
__global__ void k_eq(const float* __restrict__ e) {
    const int row  = blockIdx.x * 8 + (threadIdx.x >> 5);
    const int lane = threadIdx.x & 31;
    const float* er = e + (size_t)row * DIMS;
    uint32_t* outr = (uint32_t*)(g_e8 + (size_t)row * DIMS);
    #pragma unroll
    for (int j = 0; j < 4; j++) {
        float4 v = *(const float4*)(er + lane * 4 + 128 * j);
        int q0 = __float2int_rn(v.x * E_SCALE), q1 = __float2int_rn(v.y * E_SCALE);
        int q2 = __float2int_rn(v.z * E_SCALE), q3 = __float2int_rn(v.w * E_SCALE);
        outr[lane + 32 * j] = (q0 & 0xff) | ((q1 & 0xff) << 8)
                            | ((q2 & 0xff) << 16) | ((q3 & 0xff) << 24);
    }
}

// ---------------------------------------------------------------------------
// int8 IMMA approx-distance GEMM + margin candidate capture.
// CTA: 128 tokens x all 4096 codes; 8 warps 2(m) x 4(n), warp tile 64x64.
// 3-stage cp.async pipeline, BK=128 int8. Accumulation is EXACT (s32);
// only input quantization error -> MARGIN=2.4e-3 (14 sigma) guarantees the
// true argmin is captured. Geometry is the R4-validated pattern with 16B
// chunks = 16 int8 (k32 per chunk pair).
// ---------------------------------------------------------------------------
__global__ __launch_bounds__(256, 1) void k_vq_mma() {
    extern __shared__ char smem[];
    const uint32_t sb = smem_u32(smem);
    int* smin = (int*)(smem + SM_SCR);
    int* scnt = (int*)(smem + SM_SCR + 512);
    const int tid  = threadIdx.x;
    const int lane = tid & 31;
    const int wid  = tid >> 5;
    const int wm   = wid >> 2;
    const int wn   = wid & 3;
    const int m0   = blockIdx.x * M_TILE;

    const int8_t* __restrict__ zb = g_z8;
    const int8_t* __restrict__ eb = g_e8;

    const float zmax = __int_as_float(g_zmax_bits);
    const float inv2 = 2.0f * zmax / (127.0f * E_SCALE);

    if (tid < 128) { smin[tid] = 0x7f800000; scnt[tid] = 0; }

    // prologue: stages 0,1,2
    #pragma unroll
    for (int t0 = 0; t0 < 3; t0++) {
        const int n0 = (t0 >> 2) * N_TILE, ko = (t0 & 3) * BK;
        const uint32_t sd = sb + (uint32_t)t0 * STG;
        #pragma unroll
        for (int i = 0; i < 4; i++) {           // A: 128 rows x 8 chunks
            int q = i * 256 + tid;
            int row = q >> 3, c = q & 7;
            cp16(sd + SA_OFF + (uint32_t)(row * 128 + ((c ^ (row & 7)) * 16)),
                 zb + (size_t)(m0 + row) * DIMS + ko + c * 16);
        }
        #pragma unroll
        for (int i = 0; i < 8; i++) {           // B: 256 rows x 8 chunks
            int q = i * 256 + tid;
            int row = q >> 3, c = q & 7;
            cp16(sd + SB_OFF + (uint32_t)(row * 128 + ((c ^ (row & 7)) * 16)),
                 eb + (size_t)(n0 + row) * DIMS + ko + c * 16);
        }
        CP_COMMIT();
    }

    // lane geometry (validated in R4; chunks now 16 int8)
    const int rA  = wm * 64 + ((lane >> 3) & 1) * 8 + (lane & 7);
    const int khA = lane >> 4;
    const int rB0 = wn * 64 + ((lane >> 4) & 1) * 8 + (lane & 7);
    const int khB = (lane >> 3) & 1;

    float Szr[4][2];
    #pragma unroll
    for (int mi = 0; mi < 4; mi++)
        #pragma unroll
        for (int rh = 0; rh < 2; rh++)
            Szr[mi][rh] = g_Sz[m0 + wm * 64 + mi * 16 + (lane >> 2) + rh * 8];

    int acc[4][8][4];

    for (int t = 0; t < NITER; t++) {
        CP_WAIT(2);
        __syncthreads();

        const uint32_t sd = sb + (uint32_t)(t % 3) * STG;

        if ((t & 3) == 0) {
            #pragma unroll
            for (int mi = 0; mi < 4; mi++)
                #pragma unroll
                for (int ni = 0; ni < 8; ni++)
                    #pragma unroll
                    for (int r = 0; r < 4; r++) acc[mi][ni][r] = 0;
        }

        #pragma unroll
        for (int kk = 0; kk < 4; kk++) {
            uint32_t af[4][4];
            const int cA = kk * 2 + khA;
            #pragma unroll
            for (int mi = 0; mi < 4; mi++) {
                const int r = rA + mi * 16;
                ldsm4(af[mi], sd + SA_OFF + (uint32_t)(r * 128 + ((cA ^ (r & 7)) * 16)));
            }
            uint32_t bf[4][4];
            const int cB = kk * 2 + khB;
            #pragma unroll
            for (int nn = 0; nn < 4; nn++) {
                const int r = rB0 + nn * 16;
                ldsm4(bf[nn], sd + SB_OFF + (uint32_t)(r * 128 + ((cB ^ (r & 7)) * 16)));
            }
            #pragma unroll
            for (int mi = 0; mi < 4; mi++)
                #pragma unroll
                for (int ni = 0; ni < 8; ni++)
                    mma_s8(acc[mi][ni], af[mi],
                           bf[ni >> 1][(ni & 1) * 2], bf[ni >> 1][(ni & 1) * 2 + 1]);
        }

        // candidate capture when this 256-code tile's K is complete
        if ((t & 3) == 3) {
            const int n0g = (t >> 2) * N_TILE;
            #pragma unroll
            for (int mi = 0; mi < 4; mi++)
                #pragma unroll
                for (int rh = 0; rh < 2; rh++) {
                    float m = __int_as_float(0x7f800000);
                    #pragma unroll
                    for (int ni = 0; ni < 8; ni++)
                        #pragma unroll
                        for (int cc = 0; cc < 2; cc++) {
                            float v = __fmaf_rn(-inv2,
                                __int2float_rn(acc[mi][ni][rh * 2 + cc]), Szr[mi][rh]);
                            m = fminf(m, v);
                        }
                    int rl = wm * 64 + mi * 16 + (lane >> 2) + rh * 8;
                    atomicMin(&smin[rl], __float_as_int(m));
                }
            __syncthreads();
            #pragma unroll
            for (int mi = 0; mi < 4; mi++)
                #pragma unroll
                for (int rh = 0; rh < 2; rh++) {
                    int rl = wm * 64 + mi * 16 + (lane >> 2) + rh * 8;
                    float thr = __int_as_float(smin[rl]) + MARGIN;
                    #pragma unroll
                    for (int ni = 0; ni < 8; ni++)
                        #pragma unroll
                        for (int cc = 0; cc < 2; cc++) {
                            float v = __fmaf_rn(-inv2,
                                __int2float_rn(acc[mi][ni][rh * 2 + cc]), Szr[mi][rh]);
                            if (v < thr) {
                                int s = atomicAdd(&scnt[rl], 1);
                                if (s < MAXCAND)
                                    g_cand[(size_t)(m0 + rl) * MAXCAND + s] =
                                        n0g + wn * 64 + ni * 8 + (lane & 3) * 2 + cc;
                            }
                        }
                }
        }

        __syncthreads();
        {   // issue stage t+3 (always commit to keep group accounting static)
            const int t2 = t + 3;
            if (t2 < NITER) {
                const int n0 = (t2 >> 2) * N_TILE, ko = (t2 & 3) * BK;
                const uint32_t sd2 = sb + (uint32_t)(t2 % 3) * STG;
                #pragma unroll
                for (int i = 0; i < 4; i++) {
                    int q = i * 256 + tid;
                    int row = q >> 3, c = q & 7;
                    cp16(sd2 + SA_OFF + (uint32_t)(row * 128 + ((c ^ (row & 7)) * 16)),
                         zb + (size_t)(m0 + row) * DIMS + ko + c * 16);
                }
                #pragma unroll
                for (int i = 0; i < 8; i++) {
                    int q = i * 256 + tid;
                    int row = q >> 3, c = q & 7;
                    cp16(sd2 + SB_OFF + (uint32_t)(row * 128 + ((c ^ (row & 7)) * 16)),
                         eb + (size_t)(n0 + row) * DIMS + ko + c * 16);
                }
            }
            CP_COMMIT();
        }
    }

    __syncthreads();
    if (tid < 128) g_ccount[m0 + tid] = scnt[tid];
}

// ---------------------------------------------------------------------------
// Exact fp32 refinement: warp per token, lexicographic (distance, index) min.
// Overflowed tokens are appended to a rescue list (expected empty).
// ---------------------------------------------------------------------------
__global__ void k_refine(const float* __restrict__ z, const float* __restrict__ emb) {
    const int row  = blockIdx.x * 8 + (threadIdx.x >> 5);
    const int lane = threadIdx.x & 31;
    const int cnt  = g_ccount[row];

    if (cnt > MAXCAND) {
        if (lane == 0) g_ovf[atomicAdd(&g_ovf_n, 1)] = row;
        return;
    }

    const float Sz = g_Sz[row];
    float zr[16];
    const float* zp = z + (size_t)row * DIMS;
    #pragma unroll
    for (int i = 0; i < 16; i++) zr[i] = zp[lane + 32 * i];

    float bv = __int_as_float(0x7f800000);
    int   bi = 0;
    for (int j = 0; j < cnt; j++) {
        int c = g_cand[(size_t)row * MAXCAND + j];
        const float* er = emb + (size_t)c * DIMS;
        float s = 0.0f;
        #pragma unroll
        for (int i = 0; i < 16; i++) s = __fmaf_rn(zr[i], er[lane + 32 * i], s);
        #pragma unroll
        for (int o = 16; o; o >>= 1) s += __shfl_xor_sync(0xffffffffu, s, o);
        float d = __fmaf_rn(-2.0f, s, Sz);
        if (d < bv || (d == bv && c < bi)) { bv = d; bi = c; }
    }
    if (lane == 0) g_best[row] = bi;
}

// Full-scan rescue for overflow tokens (block per token, grid-stride).
__global__ void k_rescue(const float* __restrict__ z, const float* __restrict__ emb) {
    const int n = g_ovf_n;
    __shared__ float sv[8];
    __shared__ int   si[8];
    for (int i = blockIdx.x; i < n; i += gridDim.x) {
        const int row  = g_ovf[i];
        const int wid  = threadIdx.x >> 5;
        const int lane = threadIdx.x & 31;
        const float Sz = g_Sz[row];
        float zr[16];
        const float* zp = z + (size_t)row * DIMS;
        #pragma unroll
        for (int k = 0; k < 16; k++) zr[k] = zp[lane + 32 * k];
        float bv = __int_as_float(0x7f800000);
        int   bi = 0;
        for (int c = wid * 512; c < wid * 512 + 512; c++) {
            const float* er = emb + (size_t)c * DIMS;
            float s = 0.0f;
            #pragma unroll
            for (int k = 0; k < 16; k++) s = __fmaf_rn(zr[k], er[lane + 32 * k], s);
            #pragma unroll
            for (int o = 16; o; o >>= 1) s += __shfl_xor_sync(0xffffffffu, s, o);
            float d = __fmaf_rn(-2.0f, s, Sz);
            if (d < bv || (d == bv && c < bi)) { bv = d; bi = c; }
        }
        if (lane == 0) { sv[wid] = bv; si[wid] = bi; }
        __syncthreads();
        if (threadIdx.x == 0) {
            float v = sv[0]; int ii = si[0];
            #pragma unroll
            for (int w = 1; w < 8; w++)
                if (sv[w] < v || (sv[w] == v && si[w] < ii)) { v = sv[w]; ii = si[w]; }
            g_best[row] = ii;
        }
        __syncthreads();
    }
}

// ---------------------------------------------------------------------------
// Gather + straight-through output + loss + histogram. 2 rows per warp (MLP).
// ---------------------------------------------------------------------------
__global__ void k_gather(const float* __restrict__ z,
                         const float* __restrict__ emb,
                         float* __restrict__ out) {
    const int warp = threadIdx.x >> 5;
    const int lane = threadIdx.x & 31;
    const int row0 = blockIdx.x * 16 + warp * 2;

    double s = 0.0;
    #pragma unroll
    for (int rr = 0; rr < 2; rr++) {
        const int row = row0 + rr;
        const int idx = g_best[row];
        const float4* zr = (const float4*)(z   + (size_t)row * DIMS);
        const float4* er = (const float4*)(emb + (size_t)idx * DIMS);
        float4* orow = (float4*)(out + (size_t)row * DIMS);
        #pragma unroll
        for (int j = 0; j < 4; j++) {
            float4 q  = er[lane + 32 * j];
            float4 zz = zr[lane + 32 * j];
            float4 o;
            float t;
            t = __fsub_rn(q.x, zz.x); o.x = __fadd_rn(zz.x, t); s += (double)t * t;
            t = __fsub_rn(q.y, zz.y); o.y = __fadd_rn(zz.y, t); s += (double)t * t;
            t = __fsub_rn(q.z, zz.z); o.z = __fadd_rn(zz.z, t); s += (double)t * t;
            t = __fsub_rn(q.w, zz.w); o.w = __fadd_rn(zz.w, t); s += (double)t * t;
            orow[lane + 32 * j] = o;
        }
        if (lane == 0) atomicAdd(&g_counts[idx], 1);
    }
    #pragma unroll
    for (int o = 16; o; o >>= 1) s += __shfl_down_sync(0xffffffffu, s, o);

    __shared__ double sh[8];
    if (lane == 0) sh[warp] = s;
    __syncthreads();
    if (threadIdx.x == 0) {
        double tot = 0.0;
        #pragma unroll
        for (int w = 0; w < 8; w++) tot += sh[w];
        atomicAdd(&g_loss, tot);
    }
}

__global__ void k_final(float* __restrict__ out, int loss_pos) {
    __shared__ double sh[8];
    const int tid = threadIdx.x;
    double h = 0.0;
    for (int i = tid; i < KC; i += 256) {
        double p = (double)g_counts[i] / (double)NT;
        h += p * log(p + 1e-10);
    }
    #pragma unroll
    for (int o = 16; o; o >>= 1) h += __shfl_down_sync(0xffffffffu, h, o);
    if ((tid & 31) == 0) sh[tid >> 5] = h;
    __syncthreads();
    if (tid == 0) {
        double t = 0.0;
        #pragma unroll
        for (int w = 0; w < 8; w++) t += sh[w];
        double mean = g_loss / ((double)NT * (double)DIMS);
        out[loss_pos]     = (float)(1.25 * mean);
        out[loss_pos + 1] = (float)exp(-t);
    }
}

// ---------------------------------------------------------------------------
extern "C" void kernel_launch(void* const* d_in, const int* in_sizes, int n_in,
                              void* d_out, int out_size) {
    const float* z   = (const float*)d_in[0];
    const float* emb = (const float*)d_in[1];
    if (n_in >= 2 && in_sizes[0] == KC * DIMS && in_sizes[1] == NT * DIMS) {
        z   = (const float*)d_in[1];
        emb = (const float*)d_in[0];
    }
    float* out = (float*)d_out;

    cudaFuncSetAttribute(k_vq_mma, cudaFuncAttributeMaxDynamicSharedMemorySize,
                         SM_TOTAL);

    k_init<<<16, 256>>>();
    k_zmax<<<256, 256>>>(z);
    k_zq<<<NT / 8, 256>>>(z);
    k_eq<<<KC / 8, 256>>>(emb);
    k_vq_mma<<<NT / M_TILE, 256, SM_TOTAL>>>();
    k_refine<<<NT / 8, 256>>>(z, emb);
    k_rescue<<<16, 256>>>(z, emb);
    k_gather<<<NT / 16, 256>>>(z, emb, out);
    k_final<<<1, 256>>>(out, out_size - 2);
}

// round 6
// speedup vs baseline: 4.1717x; 4.1717x over previous
#include <cuda_runtime.h>
#include <cuda_fp16.h>
#include <math.h>
#include <stdint.h>

#define NT   32768
#define DIMS 512
#define KC   4096

#define M_TILE 128
#define N_TILE 256
#define BK     64
#define NITER  ((KC / N_TILE) * (DIMS / BK))   // 16 * 8 = 128
#define MARGIN 2.5e-4f
#define MAXCAND 32
#define THREADS 512

// SMEM stage: A 128x64 fp16 (16KB) + B 256x64 fp16 (32KB) = 48KB; 3 stages.
#define SA_OFF   0
#define SB_OFF   16384
#define STG      49152
#define SM_SCR   (3 * STG)            // smin(512) + scnt(512)
#define SM_TOTAL (SM_SCR + 1024)      // 148480

// ---------------- scratch (device globals; no mallocs allowed) ----------------
__device__ float   g_Sz[NT];
__device__ int     g_counts[KC];
__device__ double  g_loss;
__device__ __half  g_z1[NT * DIMS];
__device__ __half  g_e1[KC * DIMS];
__device__ int     g_cand[NT * MAXCAND];
__device__ int     g_ccount[NT];

// ---------------- PTX helpers (compute_103-safe) ----------------
__device__ __forceinline__ uint32_t smem_u32(const void* p) {
    uint32_t a;
    asm("{ .reg .u64 t; cvta.to.shared.u64 t, %1; cvt.u32.u64 %0, t; }" : "=r"(a) : "l"(p));
    return a;
}
__device__ __forceinline__ void cp16(uint32_t dst, const void* src) {
    asm volatile("cp.async.cg.shared.global [%0], [%1], 16;" :: "r"(dst), "l"(src) : "memory");
}
#define CP_COMMIT() asm volatile("cp.async.commit_group;" ::: "memory")
#define CP_WAIT(n)  asm volatile("cp.async.wait_group %0;" :: "n"(n) : "memory")

__device__ __forceinline__ void ldsm4(uint32_t* r, uint32_t addr) {
    asm volatile("ldmatrix.sync.aligned.m8n8.x4.shared.b16 {%0,%1,%2,%3}, [%4];"
                 : "=r"(r[0]), "=r"(r[1]), "=r"(r[2]), "=r"(r[3]) : "r"(addr));
}
__device__ __forceinline__ void mma16816(float* d, const uint32_t* a,
                                         uint32_t b0, uint32_t b1) {
    asm volatile(
        "mma.sync.aligned.m16n8k16.row.col.f32.f16.f16.f32 "
        "{%0,%1,%2,%3}, {%4,%5,%6,%7}, {%8,%9}, {%0,%1,%2,%3};"
        : "+f"(d[0]), "+f"(d[1]), "+f"(d[2]), "+f"(d[3])
        : "r"(a[0]), "r"(a[1]), "r"(a[2]), "r"(a[3]), "r"(b0), "r"(b1));
}

// ---------------------------------------------------------------------------
__global__ void k_init() {
    int t = blockIdx.x * blockDim.x + threadIdx.x;
    if (t < KC) g_counts[t] = 0;
    if (t == 0) g_loss = 0.0;
}

// Row norms of z in fp64, rounded to fp32 (R1-verified numerics).
__global__ void k_znorm(const float* __restrict__ z) {
    int row  = blockIdx.x * 8 + (threadIdx.x >> 5);
    int lane = threadIdx.x & 31;
    const float* zr = z + (size_t)row * DIMS;
    double s = 0.0;
    #pragma unroll
    for (int i = 0; i < DIMS / 32; i++) {
        float v = zr[lane + 32 * i];
        s += (double)v * (double)v;
    }
    #pragma unroll
    for (int o = 16; o; o >>= 1) s += __shfl_down_sync(0xffffffffu, s, o);
    if (lane == 0) g_Sz[row] = (float)s;
}

// fp32 -> fp16 (rn), 8 elems/thread.
__global__ void k_cvt16(const float* __restrict__ x, __half* __restrict__ y, int n8) {
    int i = blockIdx.x * blockDim.x + threadIdx.x;
    if (i >= n8) return;
    float4 a = ((const float4*)x)[i * 2 + 0];
    float4 b = ((const float4*)x)[i * 2 + 1];
    uint4 o;
    __half2 p;
    p = __halves2half2(__float2half_rn(a.x), __float2half_rn(a.y)); o.x = *(uint32_t*)&p;
    p = __halves2half2(__float2half_rn(a.z), __float2half_rn(a.w)); o.y = *(uint32_t*)&p;
    p = __halves2half2(__float2half_rn(b.x), __float2half_rn(b.y)); o.z = *(uint32_t*)&p;
    p = __halves2half2(__float2half_rn(b.z), __float2half_rn(b.w)); o.w = *(uint32_t*)&p;
    ((uint4*)y)[i] = o;
}

// ---------------------------------------------------------------------------
// fp16 mma.sync approx-distance GEMM + margin candidate capture.
// CTA: 128 tokens x all 4096 codes; 16 warps as 4(m) x 4(n); warp tile 32x64.
// 3-stage cp.async pipeline (absorbs the capture-epilogue bubble).
// ---------------------------------------------------------------------------
__global__ __launch_bounds__(THREADS, 1) void k_vq_mma() {
    extern __shared__ char smem[];
    const uint32_t sb = smem_u32(smem);
    int*  smin = (int*)(smem + SM_SCR);
    int*  scnt = (int*)(smem + SM_SCR + 512);
    const int tid  = threadIdx.x;
    const int lane = tid & 31;
    const int wid  = tid >> 5;
    const int wm   = wid >> 2;     // 0..3 (m)
    const int wn   = wid & 3;      // 0..3 (n)
    const int m0   = blockIdx.x * M_TILE;

    const __half* __restrict__ zb = g_z1;
    const __half* __restrict__ eb = g_e1;

    if (tid < 128) { smin[tid] = 0x7f800000; scnt[tid] = 0; }

    // prologue: issue stages 0,1,2
    #pragma unroll
    for (int t0 = 0; t0 < 3; t0++) {
        const int n0 = (t0 >> 3) * N_TILE, ko = (t0 & 7) * BK;
        const uint32_t sd = sb + (uint32_t)t0 * STG;
        #pragma unroll
        for (int i = 0; i < 2; i++) {           // A: 128 rows x 8 chunks = 1024
            int q = i * THREADS + tid;
            int row = q >> 3, c = q & 7;
            cp16(sd + SA_OFF + (uint32_t)(row * 128 + ((c ^ (row & 7)) * 16)),
                 zb + (size_t)(m0 + row) * DIMS + ko + c * 8);
        }
        #pragma unroll
        for (int i = 0; i < 4; i++) {           // B: 256 rows x 8 chunks = 2048
            int q = i * THREADS + tid;
            int row = q >> 3, c = q & 7;
            cp16(sd + SB_OFF + (uint32_t)(row * 128 + ((c ^ (row & 7)) * 16)),
                 eb + (size_t)(n0 + row) * DIMS + ko + c * 8);
        }
        CP_COMMIT();
    }

    // ldmatrix lane geometry (R4-validated)
    const int rA  = wm * 32 + ((lane >> 3) & 1) * 8 + (lane & 7);
    const int khA = lane >> 4;                 // 0..1
    const int rB0 = wn * 64 + ((lane >> 4) & 1) * 8 + (lane & 7);
    const int khB = (lane >> 3) & 1;

    float Szr[2][2];
    #pragma unroll
    for (int mi = 0; mi < 2; mi++)
        #pragma unroll
        for (int rh = 0; rh < 2; rh++)
            Szr[mi][rh] = g_Sz[m0 + wm * 32 + mi * 16 + (lane >> 2) + rh * 8];

    float acc[2][8][4];

    for (int t = 0; t < NITER; t++) {
        CP_WAIT(2);
        __syncthreads();

        const uint32_t sd = sb + (uint32_t)(t % 3) * STG;

        if ((t & 7) == 0) {
            #pragma unroll
            for (int mi = 0; mi < 2; mi++)
                #pragma unroll
                for (int ni = 0; ni < 8; ni++)
                    #pragma unroll
                    for (int r = 0; r < 4; r++) acc[mi][ni][r] = 0.0f;
        }

        #pragma unroll
        for (int kk = 0; kk < 4; kk++) {
            uint32_t af[2][4];
            const int cA = kk * 2 + khA;
            #pragma unroll
            for (int mi = 0; mi < 2; mi++) {
                const int r = rA + mi * 16;
                ldsm4(af[mi], sd + SA_OFF + (uint32_t)(r * 128 + ((cA ^ (r & 7)) * 16)));
            }
            uint32_t bf[4][4];
            const int cB = kk * 2 + khB;
            #pragma unroll
            for (int nn = 0; nn < 4; nn++) {
                const int r = rB0 + nn * 16;
                ldsm4(bf[nn], sd + SB_OFF + (uint32_t)(r * 128 + ((cB ^ (r & 7)) * 16)));
            }
            #pragma unroll
            for (int mi = 0; mi < 2; mi++)
                #pragma unroll
                for (int ni = 0; ni < 8; ni++)
                    mma16816(acc[mi][ni], af[mi],
                             bf[ni >> 1][(ni & 1) * 2], bf[ni >> 1][(ni & 1) * 2 + 1]);
        }

        // candidate-capture epilogue when this 256-code tile's K is complete
        if ((t & 7) == 7) {
            const int n0g = (t >> 3) * N_TILE;
            #pragma unroll
            for (int mi = 0; mi < 2; mi++)
                #pragma unroll
                for (int rh = 0; rh < 2; rh++) {
                    float m = __int_as_float(0x7f800000);
                    #pragma unroll
                    for (int ni = 0; ni < 8; ni++)
                        #pragma unroll
                        for (int cc = 0; cc < 2; cc++) {
                            float v = __fmaf_rn(-2.0f, acc[mi][ni][rh * 2 + cc],
                                                Szr[mi][rh]);
                            m = fminf(m, v);
                        }
                    int rl = wm * 32 + mi * 16 + (lane >> 2) + rh * 8;
                    atomicMin(&smin[rl], __float_as_int(m));
                }
            __syncthreads();
            #pragma unroll
            for (int mi = 0; mi < 2; mi++)
                #pragma unroll
                for (int rh = 0; rh < 2; rh++) {
                    int rl = wm * 32 + mi * 16 + (lane >> 2) + rh * 8;
                    float thr = __int_as_float(smin[rl]) + MARGIN;
                    #pragma unroll
                    for (int ni = 0; ni < 8; ni++)
                        #pragma unroll
                        for (int cc = 0; cc < 2; cc++) {
                            float v = __fmaf_rn(-2.0f, acc[mi][ni][rh * 2 + cc],
                                                Szr[mi][rh]);
                            if (v < thr) {
                                int s = atomicAdd(&scnt[rl], 1);
                                if (s < MAXCAND)
                                    g_cand[(size_t)(m0 + rl) * MAXCAND + s] =
                                        n0g + wn * 64 + ni * 8 + (lane & 3) * 2 + cc;
                            }
                        }
                }
        }

        __syncthreads();
        {   // issue stage t+3 (always commit: static group accounting)
            const int t2 = t + 3;
            if (t2 < NITER) {
                const int n0 = (t2 >> 3) * N_TILE, ko = (t2 & 7) * BK;
                const uint32_t sd2 = sb + (uint32_t)(t2 % 3) * STG;
                #pragma unroll
                for (int i = 0; i < 2; i++) {
                    int q = i * THREADS + tid;
                    int row = q >> 3, c = q & 7;
                    cp16(sd2 + SA_OFF + (uint32_t)(row * 128 + ((c ^ (row & 7)) * 16)),
                         zb + (size_t)(m0 + row) * DIMS + ko + c * 8);
                }
                #pragma unroll
                for (int i = 0; i < 4; i++) {
                    int q = i * THREADS + tid;
                    int row = q >> 3, c = q & 7;
                    cp16(sd2 + SB_OFF + (uint32_t)(row * 128 + ((c ^ (row & 7)) * 16)),
                         eb + (size_t)(n0 + row) * DIMS + ko + c * 8);
                }
            }
            CP_COMMIT();
        }
    }

    __syncthreads();
    if (tid < 128) g_ccount[m0 + tid] = scnt[tid];
}

// ---------------------------------------------------------------------------
// Fused exact refinement + gather + loss + histogram. Warp per token.
// Exact fp32 dots over candidates (lexicographic (d, idx) min; full rescan on
// overflow), then straight-through output written from the z already in regs.
// ---------------------------------------------------------------------------
__global__ void k_refine_gather(const float* __restrict__ z,
                                const float* __restrict__ emb,
                                float* __restrict__ out) {
    const int warp = threadIdx.x >> 5;
    const int lane = threadIdx.x & 31;
    const int row  = blockIdx.x * 8 + warp;
    const int cnt  = g_ccount[row];
    const float Sz = g_Sz[row];

    float zr[16];
    const float* zp = z + (size_t)row * DIMS;
    #pragma unroll
    for (int i = 0; i < 16; i++) zr[i] = zp[lane + 32 * i];

    const bool ovf = (cnt > MAXCAND);
    const int n = ovf ? KC : cnt;
    float bv = __int_as_float(0x7f800000);
    int   bi = 0;

    for (int j = 0; j < n; j++) {
        int c = ovf ? j : g_cand[(size_t)row * MAXCAND + j];
        const float* er = emb + (size_t)c * DIMS;
        float s = 0.0f;
        #pragma unroll
        for (int i = 0; i < 16; i++) s = __fmaf_rn(zr[i], er[lane + 32 * i], s);
        #pragma unroll
        for (int o = 16; o; o >>= 1) s += __shfl_xor_sync(0xffffffffu, s, o);
        float d = __fmaf_rn(-2.0f, s, Sz);
        if (d < bv || (d == bv && c < bi)) { bv = d; bi = c; }
    }

    // gather + straight-through + loss, reusing zr registers
    const float* er = emb + (size_t)bi * DIMS;
    float* orow = out + (size_t)row * DIMS;
    double s = 0.0;
    #pragma unroll
    for (int i = 0; i < 16; i++) {
        float q = er[lane + 32 * i];
        float t = __fsub_rn(q, zr[i]);
        orow[lane + 32 * i] = __fadd_rn(zr[i], t);
        s += (double)t * t;
    }
    #pragma unroll
    for (int o = 16; o; o >>= 1) s += __shfl_down_sync(0xffffffffu, s, o);

    __shared__ double sh[8];
    if (lane == 0) {
        sh[warp] = s;
        atomicAdd(&g_counts[bi], 1);
    }
    __syncthreads();
    if (threadIdx.x == 0) {
        double tot = 0.0;
        #pragma unroll
        for (int w = 0; w < 8; w++) tot += sh[w];
        atomicAdd(&g_loss, tot);
    }
}

__global__ void k_final(float* __restrict__ out, int loss_pos) {
    __shared__ double sh[8];
    const int tid = threadIdx.x;
    double h = 0.0;
    for (int i = tid; i < KC; i += 256) {
        double p = (double)g_counts[i] / (double)NT;
        h += p * log(p + 1e-10);
    }
    #pragma unroll
    for (int o = 16; o; o >>= 1) h += __shfl_down_sync(0xffffffffu, h, o);
    if ((tid & 31) == 0) sh[tid >> 5] = h;
    __syncthreads();
    if (tid == 0) {
        double t = 0.0;
        #pragma unroll
        for (int w = 0; w < 8; w++) t += sh[w];
        double mean = g_loss / ((double)NT * (double)DIMS);
        out[loss_pos]     = (float)(1.25 * mean);
        out[loss_pos + 1] = (float)exp(-t);
    }
}

// ---------------------------------------------------------------------------
extern "C" void kernel_launch(void* const* d_in, const int* in_sizes, int n_in,
                              void* d_out, int out_size) {
    const float* z   = (const float*)d_in[0];
    const float* emb = (const float*)d_in[1];
    if (n_in >= 2 && in_sizes[0] == KC * DIMS && in_sizes[1] == NT * DIMS) {
        z   = (const float*)d_in[1];
        emb = (const float*)d_in[0];
    }
    float* out = (float*)d_out;

    cudaFuncSetAttribute(k_vq_mma, cudaFuncAttributeMaxDynamicSharedMemorySize,
                         SM_TOTAL);

    __half *z1, *e1;
    cudaGetSymbolAddress((void**)&z1, g_z1);
    cudaGetSymbolAddress((void**)&e1, g_e1);

    k_init<<<16, 256>>>();
    k_znorm<<<NT / 8, 256>>>(z);
    k_cvt16<<<(NT * DIMS / 8) / 256, 256>>>(z, z1, NT * DIMS / 8);
    k_cvt16<<<(KC * DIMS / 8) / 256, 256>>>(emb, e1, KC * DIMS / 8);
    k_vq_mma<<<NT / M_TILE, THREADS, SM_TOTAL>>>();
    k_refine_gather<<<NT / 8, 256>>>(z, emb, out);
    k_final<<<1, 256>>>(out, out_size - 2);
}

// round 7
// speedup vs baseline: 4.2970x; 1.0300x over previous
#include <cuda_runtime.h>
#include <cuda_fp16.h>
#include <math.h>
#include <stdint.h>

#define NT   32768
#define DIMS 512
#define KC   4096

#define M_TILE 128
#define N_TILE 256
#define BK     64
#define NQ_CODES 1024                           // codes per work unit
#define UNITS ((NT / M_TILE) * (KC / NQ_CODES)) // 256 * 4 = 1024
#define ITERS 32                                // 4 n-tiles * 8 k-chunks
#define MARGIN 2.5e-4f
#define MAXCAND 64
#define THREADS 512

// SMEM: A persistent 128x512 fp16 (128KB) + 3 B stages (32KB each) = 224KB
#define SA_OFF   0
#define SB_OFF   131072
#define BSTG     32768
#define SM_TOTAL (131072 + 3 * BSTG)            // 229376

// ---------------- scratch (device globals; no mallocs allowed) ----------------
__device__ float   g_Sz[NT];
__device__ int     g_counts[KC];
__device__ double  g_loss;
__device__ __half  g_z1[NT * DIMS];
__device__ __half  g_e1[KC * DIMS];
__device__ int     g_cand[NT * MAXCAND];
__device__ int     g_cc[NT];
__device__ int     g_min[NT];

// ---------------- PTX helpers (compute_103-safe) ----------------
__device__ __forceinline__ uint32_t smem_u32(const void* p) {
    uint32_t a;
    asm("{ .reg .u64 t; cvta.to.shared.u64 t, %1; cvt.u32.u64 %0, t; }" : "=r"(a) : "l"(p));
    return a;
}
__device__ __forceinline__ void cp16(uint32_t dst, const void* src) {
    asm volatile("cp.async.cg.shared.global [%0], [%1], 16;" :: "r"(dst), "l"(src) : "memory");
}
#define CP_COMMIT() asm volatile("cp.async.commit_group;" ::: "memory")
#define CP_WAIT(n)  asm volatile("cp.async.wait_group %0;" :: "n"(n) : "memory")

__device__ __forceinline__ void ldsm4(uint32_t* r, uint32_t addr) {
    asm volatile("ldmatrix.sync.aligned.m8n8.x4.shared.b16 {%0,%1,%2,%3}, [%4];"
                 : "=r"(r[0]), "=r"(r[1]), "=r"(r[2]), "=r"(r[3]) : "r"(addr));
}
__device__ __forceinline__ void mma16816(float* d, const uint32_t* a,
                                         uint32_t b0, uint32_t b1) {
    asm volatile(
        "mma.sync.aligned.m16n8k16.row.col.f32.f16.f16.f32 "
        "{%0,%1,%2,%3}, {%4,%5,%6,%7}, {%8,%9}, {%0,%1,%2,%3};"
        : "+f"(d[0]), "+f"(d[1]), "+f"(d[2]), "+f"(d[3])
        : "r"(a[0]), "r"(a[1]), "r"(a[2]), "r"(a[3]), "r"(b0), "r"(b1));
}

// ---------------------------------------------------------------------------
__global__ void k_init() {
    int t = blockIdx.x * blockDim.x + threadIdx.x;   // 32768 threads
    if (t < KC) g_counts[t] = 0;
    g_min[t] = 0x7f800000;
    g_cc[t] = 0;
    if (t == 0) g_loss = 0.0;
}

// Fused: fp64 row norm + fp16 convert of z. Warp per row.
__global__ void k_zprep(const float* __restrict__ z, __half* __restrict__ z1) {
    const int row  = blockIdx.x * 8 + (threadIdx.x >> 5);
    const int lane = threadIdx.x & 31;
    const float4* zr = (const float4*)(z + (size_t)row * DIMS);
    uint2* orow = (uint2*)(z1 + (size_t)row * DIMS);
    double s = 0.0;
    #pragma unroll
    for (int j = 0; j < 4; j++) {
        float4 v = zr[lane + 32 * j];
        s += (double)v.x * v.x + (double)v.y * v.y
           + (double)v.z * v.z + (double)v.w * v.w;
        __half2 h01 = __halves2half2(__float2half_rn(v.x), __float2half_rn(v.y));
        __half2 h23 = __halves2half2(__float2half_rn(v.z), __float2half_rn(v.w));
        uint2 o; o.x = *(uint32_t*)&h01; o.y = *(uint32_t*)&h23;
        orow[lane + 32 * j] = o;
    }
    #pragma unroll
    for (int o = 16; o; o >>= 1) s += __shfl_down_sync(0xffffffffu, s, o);
    if (lane == 0) g_Sz[row] = (float)s;
}

// fp32 -> fp16 (rn), 8 elems/thread (emb).
__global__ void k_cvt16(const float* __restrict__ x, __half* __restrict__ y, int n8) {
    int i = blockIdx.x * blockDim.x + threadIdx.x;
    if (i >= n8) return;
    float4 a = ((const float4*)x)[i * 2 + 0];
    float4 b = ((const float4*)x)[i * 2 + 1];
    uint4 o;
    __half2 p;
    p = __halves2half2(__float2half_rn(a.x), __float2half_rn(a.y)); o.x = *(uint32_t*)&p;
    p = __halves2half2(__float2half_rn(a.z), __float2half_rn(a.w)); o.y = *(uint32_t*)&p;
    p = __halves2half2(__float2half_rn(b.x), __float2half_rn(b.y)); o.z = *(uint32_t*)&p;
    p = __halves2half2(__float2half_rn(b.z), __float2half_rn(b.w)); o.w = *(uint32_t*)&p;
    ((uint4*)y)[i] = o;
}

// ---------------------------------------------------------------------------
// Persistent-CTA fp16 mma.sync approx GEMM + margin candidate capture.
// Work unit = 128 tokens x 1024 codes. A tile persists in SMEM for the unit;
// B streams through a 3-stage cp.async ring with ONE __syncthreads per iter.
// Capture state (running min / count) is global: atomicMin + __ldcg snapshot
// (any snapshot >= final min -> capture superset still contains true argmin).
// ---------------------------------------------------------------------------
__global__ __launch_bounds__(THREADS, 1) void k_vq_mma() {
    extern __shared__ char smem[];
    const uint32_t sb = smem_u32(smem);
    const int tid  = threadIdx.x;
    const int lane = tid & 31;
    const int wid  = tid >> 5;
    const int wm   = wid >> 2;     // 0..3 (m)
    const int wn   = wid & 3;      // 0..3 (n)

    const __half* __restrict__ zb = g_z1;
    const __half* __restrict__ eb = g_e1;

    // ldmatrix lane geometry (R4/R6-validated)
    const int rA  = wm * 32 + ((lane >> 3) & 1) * 8 + (lane & 7);
    const int khA = lane >> 4;
    const int rB0 = wn * 64 + ((lane >> 4) & 1) * 8 + (lane & 7);
    const int khB = (lane >> 3) & 1;

    float acc[2][8][4];

    for (int u = blockIdx.x; u < UNITS; u += gridDim.x) {
        const int m0    = (u >> 2) * M_TILE;
        const int nbase = (u & 3) * NQ_CODES;

        // ---- prologue: A (persistent) + B stages 0,1 ----
        #pragma unroll
        for (int i = 0; i < 16; i++) {          // A: 128 rows x 64 chunks
            int q = i * THREADS + tid;
            int row = q >> 6, c = q & 63;
            cp16(sb + SA_OFF + (uint32_t)(row * 1024 + ((c ^ (row & 7)) * 16)),
                 zb + (size_t)(m0 + row) * DIMS + c * 8);
        }
        CP_COMMIT();
        #pragma unroll
        for (int t0 = 0; t0 < 2; t0++) {
            const int n0 = nbase + (t0 >> 3) * N_TILE, ko = (t0 & 7) * BK;
            const uint32_t sd = sb + SB_OFF + (uint32_t)t0 * BSTG;
            #pragma unroll
            for (int i = 0; i < 4; i++) {       // B: 256 rows x 8 chunks
                int q = i * THREADS + tid;
                int row = q >> 3, c = q & 7;
                cp16(sd + (uint32_t)(row * 128 + ((c ^ (row & 7)) * 16)),
                     eb + (size_t)(n0 + row) * DIMS + ko + c * 8);
            }
            CP_COMMIT();
        }

        float Szr[2][2];
        #pragma unroll
        for (int mi = 0; mi < 2; mi++)
            #pragma unroll
            for (int rh = 0; rh < 2; rh++)
                Szr[mi][rh] = g_Sz[m0 + wm * 32 + mi * 16 + (lane >> 2) + rh * 8];

        for (int t = 0; t < ITERS; t++) {
            CP_WAIT(1);
            __syncthreads();

            // issue stage t+2 into buffer (t+2)%3 (== (t-1)%3, free after sync)
            if (t + 2 < ITERS) {
                const int t2 = t + 2;
                const int n0 = nbase + (t2 >> 3) * N_TILE, ko = (t2 & 7) * BK;
                const uint32_t sd = sb + SB_OFF + (uint32_t)(t2 % 3) * BSTG;
                #pragma unroll
                for (int i = 0; i < 4; i++) {
                    int q = i * THREADS + tid;
                    int row = q >> 3, c = q & 7;
                    cp16(sd + (uint32_t)(row * 128 + ((c ^ (row & 7)) * 16)),
                         eb + (size_t)(n0 + row) * DIMS + ko + c * 8);
                }
            }
            CP_COMMIT();

            const int kc = t & 7;               // k-chunk within DIMS
            const uint32_t sdB = sb + SB_OFF + (uint32_t)(t % 3) * BSTG;

            if (kc == 0) {
                #pragma unroll
                for (int mi = 0; mi < 2; mi++)
                    #pragma unroll
                    for (int ni = 0; ni < 8; ni++)
                        #pragma unroll
                        for (int r = 0; r < 4; r++) acc[mi][ni][r] = 0.0f;
            }

            #pragma unroll
            for (int kk = 0; kk < 4; kk++) {
                uint32_t af[2][4];
                const int cA = kc * 8 + kk * 2 + khA;
                #pragma unroll
                for (int mi = 0; mi < 2; mi++) {
                    const int r = rA + mi * 16;
                    ldsm4(af[mi], sb + SA_OFF
                                  + (uint32_t)(r * 1024 + ((cA ^ (r & 7)) * 16)));
                }
                uint32_t bf[4][4];
                const int cB = kk * 2 + khB;
                #pragma unroll
                for (int nn = 0; nn < 4; nn++) {
                    const int r = rB0 + nn * 16;
                    ldsm4(bf[nn], sdB + (uint32_t)(r * 128 + ((cB ^ (r & 7)) * 16)));
                }
                #pragma unroll
                for (int mi = 0; mi < 2; mi++)
                    #pragma unroll
                    for (int ni = 0; ni < 8; ni++)
                        mma16816(acc[mi][ni], af[mi],
                                 bf[ni >> 1][(ni & 1) * 2], bf[ni >> 1][(ni & 1) * 2 + 1]);
            }

            // capture epilogue at the end of each 256-code n-tile
            if (kc == 7) {
                const int n0g = nbase + (t >> 3) * N_TILE;
                #pragma unroll
                for (int mi = 0; mi < 2; mi++)
                    #pragma unroll
                    for (int rh = 0; rh < 2; rh++) {
                        float m = __int_as_float(0x7f800000);
                        #pragma unroll
                        for (int ni = 0; ni < 8; ni++)
                            #pragma unroll
                            for (int cc = 0; cc < 2; cc++) {
                                float v = __fmaf_rn(-2.0f, acc[mi][ni][rh * 2 + cc],
                                                    Szr[mi][rh]);
                                m = fminf(m, v);
                            }
                        int rg = m0 + wm * 32 + mi * 16 + (lane >> 2) + rh * 8;
                        atomicMin(&g_min[rg], __float_as_int(m));
                    }
                __syncthreads();    // phase1 atomics of this CTA drained
                #pragma unroll
                for (int mi = 0; mi < 2; mi++)
                    #pragma unroll
                    for (int rh = 0; rh < 2; rh++) {
                        int rg = m0 + wm * 32 + mi * 16 + (lane >> 2) + rh * 8;
                        float thr = __int_as_float(__ldcg((const int*)&g_min[rg]))
                                    + MARGIN;
                        #pragma unroll
                        for (int ni = 0; ni < 8; ni++)
                            #pragma unroll
                            for (int cc = 0; cc < 2; cc++) {
                                float v = __fmaf_rn(-2.0f, acc[mi][ni][rh * 2 + cc],
                                                    Szr[mi][rh]);
                                if (v < thr) {
                                    int s = atomicAdd(&g_cc[rg], 1);
                                    if (s < MAXCAND)
                                        g_cand[(size_t)rg * MAXCAND + s] =
                                            n0g + wn * 64 + ni * 8 + (lane & 3) * 2 + cc;
                                }
                            }
                    }
            }
        }
    }
}

// ---------------------------------------------------------------------------
// Fused exact refinement + gather + loss + histogram. Warp per token.
// ---------------------------------------------------------------------------
__global__ void k_refine_gather(const float* __restrict__ z,
                                const float* __restrict__ emb,
                                float* __restrict__ out) {
    const int warp = threadIdx.x >> 5;
    const int lane = threadIdx.x & 31;
    const int row  = blockIdx.x * 8 + warp;
    const int cnt  = g_cc[row];
    const float Sz = g_Sz[row];

    float zr[16];
    const float* zp = z + (size_t)row * DIMS;
    #pragma unroll
    for (int i = 0; i < 16; i++) zr[i] = zp[lane + 32 * i];

    const bool ovf = (cnt > MAXCAND);
    const int n = ovf ? KC : cnt;
    float bv = __int_as_float(0x7f800000);
    int   bi = 0;

    for (int j = 0; j < n; j++) {
        int c = ovf ? j : g_cand[(size_t)row * MAXCAND + j];
        const float* er = emb + (size_t)c * DIMS;
        float s = 0.0f;
        #pragma unroll
        for (int i = 0; i < 16; i++) s = __fmaf_rn(zr[i], er[lane + 32 * i], s);
        #pragma unroll
        for (int o = 16; o; o >>= 1) s += __shfl_xor_sync(0xffffffffu, s, o);
        float d = __fmaf_rn(-2.0f, s, Sz);
        if (d < bv || (d == bv && c < bi)) { bv = d; bi = c; }
    }

    const float* er = emb + (size_t)bi * DIMS;
    float* orow = out + (size_t)row * DIMS;
    double s = 0.0;
    #pragma unroll
    for (int i = 0; i < 16; i++) {
        float q = er[lane + 32 * i];
        float t = __fsub_rn(q, zr[i]);
        orow[lane + 32 * i] = __fadd_rn(zr[i], t);
        s += (double)t * t;
    }
    #pragma unroll
    for (int o = 16; o; o >>= 1) s += __shfl_down_sync(0xffffffffu, s, o);

    __shared__ double sh[8];
    if (lane == 0) {
        sh[warp] = s;
        atomicAdd(&g_counts[bi], 1);
    }
    __syncthreads();
    if (threadIdx.x == 0) {
        double tot = 0.0;
        #pragma unroll
        for (int w = 0; w < 8; w++) tot += sh[w];
        atomicAdd(&g_loss, tot);
    }
}

__global__ void k_final(float* __restrict__ out, int loss_pos) {
    __shared__ double sh[8];
    const int tid = threadIdx.x;
    double h = 0.0;
    for (int i = tid; i < KC; i += 256) {
        double p = (double)g_counts[i] / (double)NT;
        h += p * log(p + 1e-10);
    }
    #pragma unroll
    for (int o = 16; o; o >>= 1) h += __shfl_down_sync(0xffffffffu, h, o);
    if ((tid & 31) == 0) sh[tid >> 5] = h;
    __syncthreads();
    if (tid == 0) {
        double t = 0.0;
        #pragma unroll
        for (int w = 0; w < 8; w++) t += sh[w];
        double mean = g_loss / ((double)NT * (double)DIMS);
        out[loss_pos]     = (float)(1.25 * mean);
        out[loss_pos + 1] = (float)exp(-t);
    }
}

// ---------------------------------------------------------------------------
extern "C" void kernel_launch(void* const* d_in, const int* in_sizes, int n_in,
                              void* d_out, int out_size) {
    const float* z   = (const float*)d_in[0];
    const float* emb = (const float*)d_in[1];
    if (n_in >= 2 && in_sizes[0] == KC * DIMS && in_sizes[1] == NT * DIMS) {
        z   = (const float*)d_in[1];
        emb = (const float*)d_in[0];
    }
    float* out = (float*)d_out;

    cudaFuncSetAttribute(k_vq_mma, cudaFuncAttributeMaxDynamicSharedMemorySize,
                         SM_TOTAL);

    __half *z1, *e1;
    cudaGetSymbolAddress((void**)&z1, g_z1);
    cudaGetSymbolAddress((void**)&e1, g_e1);

    k_init<<<128, 256>>>();
    k_zprep<<<NT / 8, 256>>>(z, z1);
    k_cvt16<<<(KC * DIMS / 8) / 256, 256>>>(emb, e1, KC * DIMS / 8);
    k_vq_mma<<<148, THREADS, SM_TOTAL>>>();
    k_refine_gather<<<NT / 8, 256>>>(z, emb, out);
    k_final<<<1, 256>>>(out, out_size - 2);
}